// round 1
// baseline (speedup 1.0000x reference)
#include <cuda_runtime.h>

#define BB 16
#define SS 2048
#define DD 1024
#define HH 1024
#define RR 16
#define MTOT (BB*SS)   // 32768

// Scratch (module-load allocated, not runtime alloc)
__device__ float A_buf[(size_t)BB*SS*HH];   // sigmoid(x@Wa^T + ba)
__device__ float U_buf[(size_t)BB*SS*HH];   // x@Wu^T + bu
__device__ float G_buf[(size_t)BB*SS*RR];   // x@Wg^T + bg

// ---------------------------------------------------------------------------
// Kernel 1: fused projection GEMM for A (with sigmoid) and U.
// C[m, n] = sum_d x[m,d] * W[n,d] + bias[n], n in [0,2048): n<1024 -> Wa, else Wu
// ---------------------------------------------------------------------------
#define GBM 128
#define GBN 128
#define GBK 16
#define GTM 8
#define GTN 8

__global__ __launch_bounds__(256, 2)
void proj_gemm_kernel(const float* __restrict__ x,
                      const float* __restrict__ Wa, const float* __restrict__ ba,
                      const float* __restrict__ Wu, const float* __restrict__ bu)
{
    __shared__ float As[GBK][GBM + 4];
    __shared__ float Bs[GBK][GBN + 4];

    const int n0 = blockIdx.x * GBN;      // 0..1920
    const int m0 = blockIdx.y * GBM;      // 0..32640
    const bool isA = (n0 < HH);
    const float* W    = isA ? (Wa + (size_t)n0 * DD) : (Wu + (size_t)(n0 - HH) * DD);
    const float* bias = isA ? (ba + n0) : (bu + (n0 - HH));
    const int ncol0 = isA ? n0 : (n0 - HH);
    float* outbase = isA ? A_buf : U_buf;

    const int tid  = threadIdx.x;
    const int lrow = tid >> 2;            // 0..63
    const int lcol = (tid & 3) * 4;       // 0,4,8,12
    const int tx = tid & 15;
    const int ty = tid >> 4;

    float acc[GTM][GTN];
#pragma unroll
    for (int i = 0; i < GTM; i++)
#pragma unroll
        for (int j = 0; j < GTN; j++) acc[i][j] = 0.f;

    const float* xptr = x + (size_t)m0 * DD;

    for (int k0 = 0; k0 < DD; k0 += GBK) {
        // load X tile [128 x 16] transposed into As[k][m]
#pragma unroll
        for (int p = 0; p < 2; p++) {
            int row = lrow + p * 64;
            float4 v4 = *(const float4*)(xptr + (size_t)row * DD + k0 + lcol);
            As[lcol + 0][row] = v4.x;
            As[lcol + 1][row] = v4.y;
            As[lcol + 2][row] = v4.z;
            As[lcol + 3][row] = v4.w;
        }
        // load W tile [128 x 16] transposed into Bs[k][n]
#pragma unroll
        for (int p = 0; p < 2; p++) {
            int row = lrow + p * 64;
            float4 v4 = *(const float4*)(W + (size_t)row * DD + k0 + lcol);
            Bs[lcol + 0][row] = v4.x;
            Bs[lcol + 1][row] = v4.y;
            Bs[lcol + 2][row] = v4.z;
            Bs[lcol + 3][row] = v4.w;
        }
        __syncthreads();

#pragma unroll
        for (int k = 0; k < GBK; k++) {
            float af[GTM], bf[GTN];
#pragma unroll
            for (int i = 0; i < GTM; i += 4) {
                float4 a4 = *(const float4*)&As[k][ty * GTM + i];
                af[i] = a4.x; af[i+1] = a4.y; af[i+2] = a4.z; af[i+3] = a4.w;
            }
#pragma unroll
            for (int j = 0; j < GTN; j += 4) {
                float4 b4 = *(const float4*)&Bs[k][tx * GTN + j];
                bf[j] = b4.x; bf[j+1] = b4.y; bf[j+2] = b4.z; bf[j+3] = b4.w;
            }
#pragma unroll
            for (int i = 0; i < GTM; i++)
#pragma unroll
                for (int j = 0; j < GTN; j++)
                    acc[i][j] = fmaf(af[i], bf[j], acc[i][j]);
        }
        __syncthreads();
    }

    // epilogue
    float bvals[GTN];
#pragma unroll
    for (int j = 0; j < GTN; j++) bvals[j] = bias[tx * GTN + j];

#pragma unroll
    for (int i = 0; i < GTM; i++) {
        int m = m0 + ty * GTM + i;
        float* orow = outbase + (size_t)m * HH + ncol0 + tx * GTN;
#pragma unroll
        for (int j = 0; j < GTN; j += 4) {
            float4 o;
            o.x = acc[i][j + 0] + bvals[j + 0];
            o.y = acc[i][j + 1] + bvals[j + 1];
            o.z = acc[i][j + 2] + bvals[j + 2];
            o.w = acc[i][j + 3] + bvals[j + 3];
            if (isA) {
                o.x = 1.f / (1.f + __expf(-o.x));
                o.y = 1.f / (1.f + __expf(-o.y));
                o.z = 1.f / (1.f + __expf(-o.z));
                o.w = 1.f / (1.f + __expf(-o.w));
            }
            *(float4*)(orow + j) = o;
        }
    }
}

// ---------------------------------------------------------------------------
// Kernel 2: g projection. G[m, r] = sum_d x[m,d]*Wg[r,d] + bg[r]
// block: 256 threads, handles 512 m rows (2 per thread). grid = 64.
// ---------------------------------------------------------------------------
__global__ __launch_bounds__(256)
void g_gemm_kernel(const float* __restrict__ x,
                   const float* __restrict__ Wg, const float* __restrict__ bg)
{
    __shared__ float Xs[16][512];      // [d][m]
    __shared__ float Wgs[16][16];      // [d][r]

    const int m0 = blockIdx.x * 512;
    const int tid = threadIdx.x;

    float acc0[RR], acc1[RR];
#pragma unroll
    for (int r = 0; r < RR; r++) { acc0[r] = 0.f; acc1[r] = 0.f; }

    for (int d0 = 0; d0 < DD; d0 += 16) {
        // load Wg chunk transposed
        if (tid < 256) {
            int d = tid >> 4, rr = tid & 15;
            Wgs[d][rr] = Wg[(size_t)rr * DD + d0 + d];
        }
        // load X tile [512 m][16 d] transposed into Xs[d][m]
#pragma unroll
        for (int p = 0; p < 8; p++) {
            int row = (tid >> 2) + p * 64;
            int dc  = (tid & 3) * 4;
            float4 v4 = *(const float4*)(x + (size_t)(m0 + row) * DD + d0 + dc);
            Xs[dc + 0][row] = v4.x;
            Xs[dc + 1][row] = v4.y;
            Xs[dc + 2][row] = v4.z;
            Xs[dc + 3][row] = v4.w;
        }
        __syncthreads();

#pragma unroll
        for (int d = 0; d < 16; d++) {
            float xv0 = Xs[d][tid];
            float xv1 = Xs[d][tid + 256];
#pragma unroll
            for (int r = 0; r < RR; r++) {
                float wgv = Wgs[d][r];
                acc0[r] = fmaf(xv0, wgv, acc0[r]);
                acc1[r] = fmaf(xv1, wgv, acc1[r]);
            }
        }
        __syncthreads();
    }

    float bgv[RR];
#pragma unroll
    for (int r = 0; r < RR; r++) bgv[r] = bg[r];

    float* g0 = G_buf + (size_t)(m0 + tid) * RR;
    float* g1 = G_buf + (size_t)(m0 + tid + 256) * RR;
#pragma unroll
    for (int r = 0; r < RR; r += 4) {
        float4 o0, o1;
        o0.x = acc0[r+0]+bgv[r+0]; o0.y = acc0[r+1]+bgv[r+1];
        o0.z = acc0[r+2]+bgv[r+2]; o0.w = acc0[r+3]+bgv[r+3];
        o1.x = acc1[r+0]+bgv[r+0]; o1.y = acc1[r+1]+bgv[r+1];
        o1.z = acc1[r+2]+bgv[r+2]; o1.w = acc1[r+3]+bgv[r+3];
        *(float4*)(g0 + r) = o0;
        *(float4*)(g1 + r) = o1;
    }
}

// ---------------------------------------------------------------------------
// Kernel 3: sequential scan. 16 blocks (one per batch) x 1024 threads.
// s_t[h] = a_t[h]*s[h] + u_t[h] + sum_r u[h,r] * (g_t[r] * sum_h' s[h']*v[h',r])
// Phase A: thread (r = tid&15, hg = tid>>4) computes one scalar partial over
//          16 h's from smem state, folds pair via shfl_xor(16), atomicAdd into
//          svg[t&1][r] (already scaled by g_t[r]).
// Phase C: thread h updates its register state, stores to smem.
// ---------------------------------------------------------------------------
__global__ __launch_bounds__(1024, 1)
void scan_kernel(const float* __restrict__ u_mat, const float* __restrict__ v_mat,
                 float* __restrict__ out)
{
    __shared__ float s_sm[HH];
    __shared__ float svg[2][RR];

    const int b    = blockIdx.x;
    const int tid  = threadIdx.x;
    const int lane = tid & 31;
    const int r    = tid & 15;
    const int hg   = tid >> 4;

    float vreg[16], ureg[16];
#pragma unroll
    for (int k = 0; k < 16; k++) vreg[k] = v_mat[(size_t)(hg * 16 + k) * RR + r];
#pragma unroll
    for (int k = 0; k < 16; k++) ureg[k] = u_mat[(size_t)tid * RR + k];

    float s = 0.f;
    s_sm[tid] = 0.f;
    if (tid < 32) ((float*)svg)[tid] = 0.f;

    const size_t base = (size_t)b * SS;
    float g_cur = G_buf[(base + 0) * RR + r];
    __syncthreads();

    for (int t = 0; t < SS; t++) {
        // prefetch phase-C operands early (covered by phase A + barriers)
        float a_t = A_buf[(base + t) * HH + tid];
        float u_t = U_buf[(base + t) * HH + tid];

        // --- phase A: partial of (v^T s)[r] over h = hg*16 .. hg*16+15 ---
        float sv[16];
        const float4* sp = (const float4*)&s_sm[hg * 16];
        float4 s0 = sp[0], s1 = sp[1], s2 = sp[2], s3 = sp[3];
        sv[0]=s0.x; sv[1]=s0.y; sv[2]=s0.z; sv[3]=s0.w;
        sv[4]=s1.x; sv[5]=s1.y; sv[6]=s1.z; sv[7]=s1.w;
        sv[8]=s2.x; sv[9]=s2.y; sv[10]=s2.z; sv[11]=s2.w;
        sv[12]=s3.x; sv[13]=s3.y; sv[14]=s3.z; sv[15]=s3.w;

        float accA = 0.f, accB = 0.f;
#pragma unroll
        for (int k = 0; k < 16; k += 2) {
            accA = fmaf(sv[k],     vreg[k],     accA);
            accB = fmaf(sv[k + 1], vreg[k + 1], accB);
        }
        float acc = accA + accB;
        acc += __shfl_xor_sync(0xffffffffu, acc, 16);
        if (lane < 16) atomicAdd(&svg[t & 1][r], g_cur * acc);

        float g_nxt = (t + 1 < SS) ? G_buf[(base + t + 1) * RR + r] : 0.f;
        __syncthreads();

        // --- phase C: update state ---
        float cf[16];
        const float4* cp = (const float4*)&svg[t & 1][0];
        float4 c0 = cp[0], c1 = cp[1], c2 = cp[2], c3 = cp[3];
        cf[0]=c0.x; cf[1]=c0.y; cf[2]=c0.z; cf[3]=c0.w;
        cf[4]=c1.x; cf[5]=c1.y; cf[6]=c1.z; cf[7]=c1.w;
        cf[8]=c2.x; cf[9]=c2.y; cf[10]=c2.z; cf[11]=c2.w;
        cf[12]=c3.x; cf[13]=c3.y; cf[14]=c3.z; cf[15]=c3.w;

        s = fmaf(a_t, s, u_t);
        float dA = 0.f, dB = 0.f;
#pragma unroll
        for (int k = 0; k < 16; k += 2) {
            dA = fmaf(cf[k],     ureg[k],     dA);
            dB = fmaf(cf[k + 1], ureg[k + 1], dB);
        }
        s += dA + dB;
        s_sm[tid] = s;
        if (tid < 16) svg[(t + 1) & 1][tid] = 0.f;   // reset other buffer
        g_cur = g_nxt;
        __syncthreads();
    }

    out[(size_t)b * HH + tid] = s;
}

// ---------------------------------------------------------------------------
extern "C" void kernel_launch(void* const* d_in, const int* in_sizes, int n_in,
                              void* d_out, int out_size)
{
    const float* x  = (const float*)d_in[0];
    const float* Wa = (const float*)d_in[1];
    const float* ba = (const float*)d_in[2];
    const float* Wg = (const float*)d_in[3];
    const float* bg = (const float*)d_in[4];
    const float* Wu = (const float*)d_in[5];
    const float* bu = (const float*)d_in[6];
    const float* u  = (const float*)d_in[7];
    const float* v  = (const float*)d_in[8];
    float* out = (float*)d_out;

    (void)in_sizes; (void)n_in; (void)out_size;

    proj_gemm_kernel<<<dim3(2048 / GBN, MTOT / GBM), 256>>>(x, Wa, ba, Wu, bu);
    g_gemm_kernel<<<MTOT / 512, 256>>>(x, Wg, bg);
    scan_kernel<<<BB, 1024>>>(u, v, out);
}

// round 4
// speedup vs baseline: 1.8625x; 1.8625x over previous
#include <cuda_runtime.h>
#include <cuda_bf16.h>
#include <cstdint>

#define BB 16
#define SS 2048
#define DD 1024
#define HH 1024
#define RR 16
#define MTOT (BB*SS)   // 32768

// tcgen05 only exists in the arch-specific (sm_103a/sm_100a) feature set.
// The harness also runs a compute_103 base-PTX pass; give it an empty body.
#if defined(__CUDA_ARCH_FEAT_SM103_ALL) || defined(__CUDA_ARCH_FEAT_SM100_ALL)
#define HAS_TCGEN05 1
#elif defined(__CUDA_ARCH_SPECIFIC__)
#if (__CUDA_ARCH_SPECIFIC__ == 1030) || (__CUDA_ARCH_SPECIFIC__ == 1000)
#define HAS_TCGEN05 1
#else
#define HAS_TCGEN05 0
#endif
#else
#define HAS_TCGEN05 0
#endif

// Scratch (module-load allocated, not runtime alloc)
__device__ float A_buf[(size_t)BB*SS*HH];   // sigmoid(x@Wa^T + ba)
__device__ float U_buf[(size_t)BB*SS*HH];   // x@Wu^T + bu
__device__ float G_buf[(size_t)BB*SS*RR];   // x@Wg^T + bg

// ============================ PTX helpers ============================
__device__ __forceinline__ uint32_t smem_u32(const void* p) {
    uint32_t a;
    asm("{ .reg .u64 t; cvta.to.shared.u64 t, %1; cvt.u32.u64 %0, t; }" : "=r"(a) : "l"(p));
    return a;
}
#define SWZ128(o) ((o) ^ (((o) >> 3) & 0x70))

#if HAS_TCGEN05

__device__ __forceinline__ uint32_t elect_one() {
    uint32_t r;
    asm volatile("{ .reg .pred p; elect.sync _|p, 0xFFFFFFFF; selp.b32 %0, 1, 0, p; }" : "=r"(r));
    return r;
}

#define TC_ALLOC(smem_addr, ncols) \
    asm volatile("tcgen05.alloc.cta_group::1.sync.aligned.shared::cta.b32 [%0], %1;" \
                 :: "r"(smem_addr), "r"(ncols) : "memory")
#define TC_DEALLOC(tmem, ncols) \
    asm volatile("tcgen05.dealloc.cta_group::1.sync.aligned.b32 %0, %1;" :: "r"(tmem), "r"(ncols))
#define TC_COMMIT(mbar) \
    asm volatile("tcgen05.commit.cta_group::1.mbarrier::arrive::one.shared::cluster.b64 [%0];" \
                 :: "r"(mbar) : "memory")
#define TC_FENCE_AFTER()  asm volatile("tcgen05.fence::after_thread_sync;" ::: "memory")
#define TC_WAIT_LD()      asm volatile("tcgen05.wait::ld.sync.aligned;" ::: "memory")
#define FENCE_ASYNC_SHARED() asm volatile("fence.proxy.async.shared::cta;" ::: "memory")

#define MBAR_INIT(addr, cnt) \
    asm volatile("mbarrier.init.shared.b64 [%0], %1;" :: "r"(addr), "r"(cnt) : "memory")

#define MBAR_WAIT_PARITY(addr, parity) do { \
    uint32_t _mbar = (uint32_t)(addr); \
    uint32_t _par  = (uint32_t)(parity); \
    uint32_t _done; \
    asm volatile("{\n\t.reg .pred p;\n\t" \
        "mbarrier.try_wait.parity.acquire.cta.shared::cta.b64 p, [%1], %2;\n\t" \
        "selp.b32 %0, 1, 0, p;\n\t}" \
        : "=r"(_done) : "r"(_mbar), "r"(_par) : "memory"); \
    if (!_done) { \
        asm volatile("{\n\t.reg .pred P1;\n\t" \
            "WAIT_LOOP_%=:\n\t" \
            "mbarrier.try_wait.parity.acquire.cta.shared::cta.b64 P1, [%0], %1, 0x989680;\n\t" \
            "@P1 bra.uni WAIT_DONE_%=;\n\t" \
            "bra.uni WAIT_LOOP_%=;\n\t" \
            "WAIT_DONE_%=:\n\t}" \
            :: "r"(_mbar), "r"(_par) : "memory"); \
    } \
} while (0)

#define TC_LD_32X32B_X32(r, tmem_addr) \
    asm volatile( \
        "tcgen05.ld.sync.aligned.32x32b.x32.b32 " \
        "{%0, %1, %2, %3, %4, %5, %6, %7, " \
        " %8, %9, %10, %11, %12, %13, %14, %15, " \
        " %16, %17, %18, %19, %20, %21, %22, %23, " \
        " %24, %25, %26, %27, %28, %29, %30, %31}, [%32];" \
        : "=r"((r)[0]),  "=r"((r)[1]),  "=r"((r)[2]),  "=r"((r)[3]), \
          "=r"((r)[4]),  "=r"((r)[5]),  "=r"((r)[6]),  "=r"((r)[7]), \
          "=r"((r)[8]),  "=r"((r)[9]),  "=r"((r)[10]), "=r"((r)[11]), \
          "=r"((r)[12]), "=r"((r)[13]), "=r"((r)[14]), "=r"((r)[15]), \
          "=r"((r)[16]), "=r"((r)[17]), "=r"((r)[18]), "=r"((r)[19]), \
          "=r"((r)[20]), "=r"((r)[21]), "=r"((r)[22]), "=r"((r)[23]), \
          "=r"((r)[24]), "=r"((r)[25]), "=r"((r)[26]), "=r"((r)[27]), \
          "=r"((r)[28]), "=r"((r)[29]), "=r"((r)[30]), "=r"((r)[31]) \
        : "r"(tmem_addr))

// SW128 K-major smem descriptor (layout=2, version=1, SBO=64, LBO=1)
__device__ __forceinline__ uint64_t make_desc_sw128(uint32_t addr) {
    const uint64_t base = (uint64_t(2) << 61) | (uint64_t(1) << 46)
                        | (uint64_t(64) << 32) | (uint64_t(1) << 16);
    return base | ((uint64_t)(addr >> 4) & 0x3FFF);
}

// SS-mode f16-kind MMA, cta_group::1
__device__ __forceinline__ void mma_f16_ss(uint32_t d, uint64_t ad, uint64_t bd,
                                           uint32_t idesc, uint32_t en) {
    asm volatile(
        "{\n\t.reg .pred p;\n\t"
        "setp.ne.u32 p, %4, 0;\n\t"
        "tcgen05.mma.cta_group::1.kind::f16 [%0], %1, %2, %3, {%5,%5,%5,%5}, p;\n\t}"
        :: "r"(d), "l"(ad), "l"(bd), "r"(idesc), "r"(en), "r"(0u) : "memory");
}

// pack two f32 -> bf16x2 (lo arg in low half)
__device__ __forceinline__ uint32_t pack_bf16x2(float lo, float hi) {
    uint32_t r;
    asm("cvt.rn.bf16x2.f32 %0, %1, %2;" : "=r"(r) : "f"(hi), "f"(lo));
    return r;
}

#endif // HAS_TCGEN05

// ============================================================================
// Kernel 1: tcgen05 split-bf16 projection GEMM (Wa‖Wu fused, sigmoid epilogue)
// C[m, n] = sum_d x[m,d] * W[n,d] + bias[n]; fp32 decomposed as hi+lo bf16.
// Tile: M=128, N=256, K-chunk=64 bf16, double buffered. 256 threads.
// ============================================================================
#define TM 128
#define TN 256
#define KC 64
#define NCHUNK (DD / KC)     // 16

#define A_HI_OFF 0
#define A_LO_OFF 16384
#define B_HI_OFF 32768
#define B_LO_OFF 65536
#define STAGE_BYTES 98304
#define STAGE_BASE  1024
#define SMEM_TOTAL  (STAGE_BASE + 2 * STAGE_BYTES)   // 197632

__global__ __launch_bounds__(256, 1)
void proj_gemm_tc(const float* __restrict__ x,
                  const float* __restrict__ Wa, const float* __restrict__ ba,
                  const float* __restrict__ Wu, const float* __restrict__ bu)
{
#if HAS_TCGEN05
    extern __shared__ char smem[];
    const uint32_t smb = smem_u32(smem);

    const uint32_t IDESC =
        (1u << 4) | (1u << 7) | (1u << 10) | ((TN / 8) << 17) | ((TM / 16) << 24);

    const int tid  = threadIdx.x;
    const int wid  = tid >> 5;
    const int lane = tid & 31;

    const int n0 = blockIdx.x * TN;       // 0..1792
    const int m0 = blockIdx.y * TM;
    const bool isA = (n0 < HH);
    const int ncol0 = isA ? n0 : (n0 - HH);
    const float* Wt   = (isA ? Wa : Wu) + (size_t)ncol0 * DD;
    const float* bias = (isA ? ba : bu) + ncol0;
    float* outb = isA ? A_buf : U_buf;

    // TMEM alloc (warp 0), 256 cols for D
    if (wid == 0) TC_ALLOC(smb + 0, 256);
    if (tid == 0) {
        MBAR_INIT(smb + 8, 1);
        MBAR_INIT(smb + 16, 1);
    }
    __syncthreads();
    uint32_t tmem_base;
    asm volatile("ld.shared.b32 %0, [%1];" : "=r"(tmem_base) : "r"(smb + 0));

    const uint32_t mb[2] = { smb + 8, smb + 16 };
    uint32_t ph[2] = { 0, 0 };

    const int arow = tid >> 1;
    const int acolg = (tid & 1) * 32;
    const float* aptr = x + (size_t)(m0 + arow) * DD + acolg;
    const float* bptr = Wt + (size_t)tid * DD;

    for (int c = 0; c < NCHUNK; ++c) {
        const int st = c & 1;
        const uint32_t sb = smb + STAGE_BASE + st * STAGE_BYTES;
        const int kc0 = c * KC;

        // issue A loads early
        float4 af4[8];
#pragma unroll
        for (int i = 0; i < 8; i++)
            af4[i] = __ldg((const float4*)(aptr + kc0 + i * 4));

        // wait until MMA from chunk c-2 released this stage
        if (c >= 2) { MBAR_WAIT_PARITY(mb[st], ph[st]); ph[st] ^= 1; }

        // ---- convert + STS A (row = tid>>1, cols acolg..acolg+31)
        {
            const uint32_t aHi = sb + A_HI_OFF, aLo = sb + A_LO_OFF;
#pragma unroll
            for (int g = 0; g < 4; g++) {
                float4 p = af4[2 * g], q = af4[2 * g + 1];
                uint32_t w0 = __float_as_uint(p.x), w1 = __float_as_uint(p.y);
                uint32_t w2 = __float_as_uint(p.z), w3 = __float_as_uint(p.w);
                uint32_t v0 = __float_as_uint(q.x), v1 = __float_as_uint(q.y);
                uint32_t v2 = __float_as_uint(q.z), v3 = __float_as_uint(q.w);
                uint32_t h0 = __byte_perm(w0, w1, 0x7632);
                uint32_t h1 = __byte_perm(w2, w3, 0x7632);
                uint32_t h2 = __byte_perm(v0, v1, 0x7632);
                uint32_t h3 = __byte_perm(v2, v3, 0x7632);
                float l0 = p.x - __uint_as_float(w0 & 0xFFFF0000u);
                float l1 = p.y - __uint_as_float(w1 & 0xFFFF0000u);
                float l2 = p.z - __uint_as_float(w2 & 0xFFFF0000u);
                float l3 = p.w - __uint_as_float(w3 & 0xFFFF0000u);
                float m0f = q.x - __uint_as_float(v0 & 0xFFFF0000u);
                float m1f = q.y - __uint_as_float(v1 & 0xFFFF0000u);
                float m2f = q.z - __uint_as_float(v2 & 0xFFFF0000u);
                float m3f = q.w - __uint_as_float(v3 & 0xFFFF0000u);
                uint32_t lo0 = pack_bf16x2(l0, l1),  lo1 = pack_bf16x2(l2, l3);
                uint32_t lo2 = pack_bf16x2(m0f, m1f), lo3 = pack_bf16x2(m2f, m3f);
                uint32_t off = SWZ128((uint32_t)(arow * 128 + (acolg + g * 8) * 2));
                asm volatile("st.shared.v4.b32 [%0], {%1,%2,%3,%4};"
                             :: "r"(aHi + off), "r"(h0), "r"(h1), "r"(h2), "r"(h3) : "memory");
                asm volatile("st.shared.v4.b32 [%0], {%1,%2,%3,%4};"
                             :: "r"(aLo + off), "r"(lo0), "r"(lo1), "r"(lo2), "r"(lo3) : "memory");
            }
        }
        // ---- convert + STS B (row = tid, 64 cols in 2 halves)
        {
            const uint32_t bHi = sb + B_HI_OFF, bLo = sb + B_LO_OFF;
#pragma unroll
            for (int hh = 0; hh < 2; hh++) {
                float4 bf4[8];
#pragma unroll
                for (int i = 0; i < 8; i++)
                    bf4[i] = __ldg((const float4*)(bptr + kc0 + hh * 32 + i * 4));
#pragma unroll
                for (int g = 0; g < 4; g++) {
                    float4 p = bf4[2 * g], q = bf4[2 * g + 1];
                    uint32_t w0 = __float_as_uint(p.x), w1 = __float_as_uint(p.y);
                    uint32_t w2 = __float_as_uint(p.z), w3 = __float_as_uint(p.w);
                    uint32_t v0 = __float_as_uint(q.x), v1 = __float_as_uint(q.y);
                    uint32_t v2 = __float_as_uint(q.z), v3 = __float_as_uint(q.w);
                    uint32_t h0 = __byte_perm(w0, w1, 0x7632);
                    uint32_t h1 = __byte_perm(w2, w3, 0x7632);
                    uint32_t h2 = __byte_perm(v0, v1, 0x7632);
                    uint32_t h3 = __byte_perm(v2, v3, 0x7632);
                    float l0 = p.x - __uint_as_float(w0 & 0xFFFF0000u);
                    float l1 = p.y - __uint_as_float(w1 & 0xFFFF0000u);
                    float l2 = p.z - __uint_as_float(w2 & 0xFFFF0000u);
                    float l3 = p.w - __uint_as_float(w3 & 0xFFFF0000u);
                    float n0f = q.x - __uint_as_float(v0 & 0xFFFF0000u);
                    float n1f = q.y - __uint_as_float(v1 & 0xFFFF0000u);
                    float n2f = q.z - __uint_as_float(v2 & 0xFFFF0000u);
                    float n3f = q.w - __uint_as_float(v3 & 0xFFFF0000u);
                    uint32_t lo0 = pack_bf16x2(l0, l1),  lo1 = pack_bf16x2(l2, l3);
                    uint32_t lo2 = pack_bf16x2(n0f, n1f), lo3 = pack_bf16x2(n2f, n3f);
                    uint32_t off = SWZ128((uint32_t)(tid * 128 + (hh * 32 + g * 8) * 2));
                    asm volatile("st.shared.v4.b32 [%0], {%1,%2,%3,%4};"
                                 :: "r"(bHi + off), "r"(h0), "r"(h1), "r"(h2), "r"(h3) : "memory");
                    asm volatile("st.shared.v4.b32 [%0], {%1,%2,%3,%4};"
                                 :: "r"(bLo + off), "r"(lo0), "r"(lo1), "r"(lo2), "r"(lo3) : "memory");
                }
            }
        }
        __syncthreads();   // STS visible to all threads

        if (wid == 0) {
            FENCE_ASYNC_SHARED();
            if (elect_one()) {
                uint64_t dAhi = make_desc_sw128(sb + A_HI_OFF);
                uint64_t dAlo = make_desc_sw128(sb + A_LO_OFF);
                uint64_t dBhi = make_desc_sw128(sb + B_HI_OFF);
                uint64_t dBlo = make_desc_sw128(sb + B_LO_OFF);
#pragma unroll
                for (int k = 0; k < 4; k++) {
                    uint32_t en0 = (c > 0 || k > 0) ? 1u : 0u;
                    mma_f16_ss(tmem_base, dAhi + k * 2, dBhi + k * 2, IDESC, en0);
                    mma_f16_ss(tmem_base, dAhi + k * 2, dBlo + k * 2, IDESC, 1u);
                    mma_f16_ss(tmem_base, dAlo + k * 2, dBhi + k * 2, IDESC, 1u);
                }
                TC_COMMIT(mb[st]);
            }
        }
    }

    // drain the last commit on each stage
    MBAR_WAIT_PARITY(mb[0], ph[0]);
    MBAR_WAIT_PARITY(mb[1], ph[1]);
    TC_FENCE_AFTER();
    __syncthreads();

    // ---- epilogue: TMEM -> (bias, sigmoid) -> smem transpose -> coalesced STG
    float* stg = (float*)(smem + STAGE_BASE);     // 128 x 65 fp32 staging
    const int half = wid >> 2;                     // col half within 64-slab
    const int subw = wid & 3;                      // TMEM subpartition rows
    const int rowl = subw * 32 + lane;

    for (int slab = 0; slab < 4; ++slab) {
        const int c0 = slab * 64;
        uint32_t regs[32];
        TC_LD_32X32B_X32(regs, tmem_base + c0 + half * 32);
        TC_WAIT_LD();
#pragma unroll
        for (int j = 0; j < 32; j++) {
            int n = c0 + half * 32 + j;
            float val = __uint_as_float(regs[j]) + __ldg(&bias[n]);
            if (isA) val = 1.f / (1.f + __expf(-val));
            stg[rowl * 65 + half * 32 + j] = val;
        }
        __syncthreads();
#pragma unroll
        for (int i = 0; i < 8; i++) {
            int idx = tid + i * 256;          // 0..2047
            int row = idx >> 4, c4 = idx & 15;
            // scalar LDS (stride 65 => float4 would be misaligned for odd rows)
            const float* src = &stg[row * 65 + c4 * 4];
            float4 vv;
            vv.x = src[0]; vv.y = src[1]; vv.z = src[2]; vv.w = src[3];
            *(float4*)(outb + (size_t)(m0 + row) * HH + ncol0 + c0 + c4 * 4) = vv;
        }
        __syncthreads();
    }

    if (wid == 0) TC_DEALLOC(tmem_base, 256);
#endif // HAS_TCGEN05
}

// ---------------------------------------------------------------------------
// Kernel 2: g projection. G[m, r] = sum_d x[m,d]*Wg[r,d] + bg[r]
// ---------------------------------------------------------------------------
__global__ __launch_bounds__(256)
void g_gemm_kernel(const float* __restrict__ x,
                   const float* __restrict__ Wg, const float* __restrict__ bg)
{
    __shared__ __align__(16) float Xs[16][512];
    __shared__ __align__(16) float Wgs[16][16];

    const int m0 = blockIdx.x * 512;
    const int tid = threadIdx.x;

    float acc0[RR], acc1[RR];
#pragma unroll
    for (int r = 0; r < RR; r++) { acc0[r] = 0.f; acc1[r] = 0.f; }

    for (int d0 = 0; d0 < DD; d0 += 16) {
        {
            int d = tid >> 4, rr = tid & 15;
            Wgs[d][rr] = Wg[(size_t)rr * DD + d0 + d];
        }
#pragma unroll
        for (int p = 0; p < 8; p++) {
            int row = (tid >> 2) + p * 64;
            int dc  = (tid & 3) * 4;
            float4 v4 = *(const float4*)(x + (size_t)(m0 + row) * DD + d0 + dc);
            Xs[dc + 0][row] = v4.x;
            Xs[dc + 1][row] = v4.y;
            Xs[dc + 2][row] = v4.z;
            Xs[dc + 3][row] = v4.w;
        }
        __syncthreads();

#pragma unroll
        for (int d = 0; d < 16; d++) {
            float xv0 = Xs[d][tid];
            float xv1 = Xs[d][tid + 256];
#pragma unroll
            for (int r = 0; r < RR; r++) {
                float wgv = Wgs[d][r];
                acc0[r] = fmaf(xv0, wgv, acc0[r]);
                acc1[r] = fmaf(xv1, wgv, acc1[r]);
            }
        }
        __syncthreads();
    }

    float bgv[RR];
#pragma unroll
    for (int r = 0; r < RR; r++) bgv[r] = bg[r];

    float* g0 = G_buf + (size_t)(m0 + tid) * RR;
    float* g1 = G_buf + (size_t)(m0 + tid + 256) * RR;
#pragma unroll
    for (int r = 0; r < RR; r += 4) {
        float4 o0, o1;
        o0.x = acc0[r+0]+bgv[r+0]; o0.y = acc0[r+1]+bgv[r+1];
        o0.z = acc0[r+2]+bgv[r+2]; o0.w = acc0[r+3]+bgv[r+3];
        o1.x = acc1[r+0]+bgv[r+0]; o1.y = acc1[r+1]+bgv[r+1];
        o1.z = acc1[r+2]+bgv[r+2]; o1.w = acc1[r+3]+bgv[r+3];
        *(float4*)(g0 + r) = o0;
        *(float4*)(g1 + r) = o1;
    }
}

// ---------------------------------------------------------------------------
// Kernel 3: sequential scan. 16 blocks (one per batch) x 1024 threads.
// s_t[h] = a_t[h]*s[h] + u_t[h] + sum_r u[h,r] * (g_t[r] * sum_h' s[h']*v[h',r])
// Reduction: per-warp partial STS + 16-warp shuffle tree (no atomics).
// ---------------------------------------------------------------------------
__global__ __launch_bounds__(1024, 1)
void scan_kernel(const float* __restrict__ u_mat, const float* __restrict__ v_mat,
                 float* __restrict__ out)
{
    __shared__ __align__(16) float s_sm[HH];
    __shared__ __align__(16) float part[32][17];
    __shared__ __align__(16) float svg[16];
    __shared__ __align__(16) float g_sm[16];

    const int b    = blockIdx.x;
    const int tid  = threadIdx.x;
    const int wid  = tid >> 5;
    const int lane = tid & 31;
    const int r    = tid & 15;
    const int hg   = tid >> 4;

    float vreg[16], ureg[16];
#pragma unroll
    for (int k = 0; k < 16; k++) vreg[k] = v_mat[(size_t)(hg * 16 + k) * RR + r];
#pragma unroll
    for (int k = 0; k < 16; k++) ureg[k] = u_mat[(size_t)tid * RR + k];

    float s = 0.f;
    s_sm[tid] = 0.f;

    const size_t base = (size_t)b * SS;
    float g_cur = G_buf[(base + 0) * RR + r];
    __syncthreads();

    for (int t = 0; t < SS; t++) {
        float a_t = A_buf[(base + t) * HH + tid];
        float u_t = U_buf[(base + t) * HH + tid];
        if (tid < 16) g_sm[tid] = g_cur;

        // --- phase A: partial of (v^T s)[r] over h = hg*16 .. hg*16+15 ---
        float sv[16];
        const float4* sp = (const float4*)&s_sm[hg * 16];
        float4 s0 = sp[0], s1 = sp[1], s2 = sp[2], s3 = sp[3];
        sv[0]=s0.x; sv[1]=s0.y; sv[2]=s0.z; sv[3]=s0.w;
        sv[4]=s1.x; sv[5]=s1.y; sv[6]=s1.z; sv[7]=s1.w;
        sv[8]=s2.x; sv[9]=s2.y; sv[10]=s2.z; sv[11]=s2.w;
        sv[12]=s3.x; sv[13]=s3.y; sv[14]=s3.z; sv[15]=s3.w;

        float accA = 0.f, accB = 0.f;
#pragma unroll
        for (int k = 0; k < 16; k += 2) {
            accA = fmaf(sv[k],     vreg[k],     accA);
            accB = fmaf(sv[k + 1], vreg[k + 1], accB);
        }
        float acc = accA + accB;
        acc += __shfl_xor_sync(0xffffffffu, acc, 16);
        if (lane < 16) part[wid][lane] = acc;

        float g_nxt = (t + 1 < SS) ? G_buf[(base + t + 1) * RR + r] : 0.f;
        __syncthreads();   // bar1: partials + g_sm visible

        // --- reduce: warp w (w<16) sums 32 partials for residual index w ---
        if (wid < 16) {
            float pv = part[lane][wid];
            pv += __shfl_xor_sync(0xffffffffu, pv, 16);
            pv += __shfl_xor_sync(0xffffffffu, pv, 8);
            pv += __shfl_xor_sync(0xffffffffu, pv, 4);
            pv += __shfl_xor_sync(0xffffffffu, pv, 2);
            pv += __shfl_xor_sync(0xffffffffu, pv, 1);
            if (lane == 0) svg[wid] = g_sm[wid] * pv;
        }
        __syncthreads();   // bar2: svg visible

        // --- phase C: update state ---
        float cf[16];
        const float4* cp = (const float4*)&svg[0];
        float4 c0 = cp[0], c1 = cp[1], c2 = cp[2], c3 = cp[3];
        cf[0]=c0.x; cf[1]=c0.y; cf[2]=c0.z; cf[3]=c0.w;
        cf[4]=c1.x; cf[5]=c1.y; cf[6]=c1.z; cf[7]=c1.w;
        cf[8]=c2.x; cf[9]=c2.y; cf[10]=c2.z; cf[11]=c2.w;
        cf[12]=c3.x; cf[13]=c3.y; cf[14]=c3.z; cf[15]=c3.w;

        s = fmaf(a_t, s, u_t);
        float dA = 0.f, dB = 0.f;
#pragma unroll
        for (int k = 0; k < 16; k += 2) {
            dA = fmaf(cf[k],     ureg[k],     dA);
            dB = fmaf(cf[k + 1], ureg[k + 1], dB);
        }
        s += dA + dB;
        s_sm[tid] = s;
        g_cur = g_nxt;
        __syncthreads();   // bar3: state visible for next phase A
    }

    out[(size_t)b * HH + tid] = s;
}

// ---------------------------------------------------------------------------
extern "C" void kernel_launch(void* const* d_in, const int* in_sizes, int n_in,
                              void* d_out, int out_size)
{
    const float* x  = (const float*)d_in[0];
    const float* Wa = (const float*)d_in[1];
    const float* ba = (const float*)d_in[2];
    const float* Wg = (const float*)d_in[3];
    const float* bg = (const float*)d_in[4];
    const float* Wu = (const float*)d_in[5];
    const float* bu = (const float*)d_in[6];
    const float* u  = (const float*)d_in[7];
    const float* v  = (const float*)d_in[8];
    float* out = (float*)d_out;

    (void)in_sizes; (void)n_in; (void)out_size;

    cudaFuncSetAttribute(proj_gemm_tc, cudaFuncAttributeMaxDynamicSharedMemorySize, SMEM_TOTAL);

    proj_gemm_tc<<<dim3(2048 / TN, MTOT / TM), 256, SMEM_TOTAL>>>(x, Wa, ba, Wu, bu);
    g_gemm_kernel<<<MTOT / 512, 256>>>(x, Wg, bg);
    scan_kernel<<<BB, 1024>>>(u, v, out);
}

// round 5
// speedup vs baseline: 2.3883x; 1.2823x over previous
#include <cuda_runtime.h>
#include <cuda_bf16.h>
#include <cstdint>

#define BB 16
#define SS 2048
#define DD 1024
#define HH 1024
#define RR 16
#define MTOT (BB*SS)   // 32768
#define NN2 2048       // Wa||Wu stacked rows

// tcgen05 only exists in the arch-specific (sm_103a/sm_100a) feature set.
// The harness also runs a compute_103 base-PTX pass; give it an empty body.
#if defined(__CUDA_ARCH_FEAT_SM103_ALL) || defined(__CUDA_ARCH_FEAT_SM100_ALL)
#define HAS_TCGEN05 1
#elif defined(__CUDA_ARCH_SPECIFIC__)
#if (__CUDA_ARCH_SPECIFIC__ == 1030) || (__CUDA_ARCH_SPECIFIC__ == 1000)
#define HAS_TCGEN05 1
#else
#define HAS_TCGEN05 0
#endif
#else
#define HAS_TCGEN05 0
#endif

// Scratch (module-load allocated, not runtime alloc)
__device__ float A_buf[(size_t)BB*SS*HH];   // sigmoid(x@Wa^T + ba)
__device__ float U_buf[(size_t)BB*SS*HH];   // x@Wu^T + bu
__device__ float G_buf[(size_t)BB*SS*RR];   // x@Wg^T + bg

// split-bf16 operand buffers (hi = truncated top16, lo = rn(x - hi))
__device__ __align__(16) __nv_bfloat16 Xhi[(size_t)MTOT*DD];
__device__ __align__(16) __nv_bfloat16 Xlo[(size_t)MTOT*DD];
__device__ __align__(16) __nv_bfloat16 Whi[(size_t)NN2*DD];
__device__ __align__(16) __nv_bfloat16 Wlo[(size_t)NN2*DD];

// ============================ helpers ============================
__device__ __forceinline__ uint32_t smem_u32(const void* p) {
    uint32_t a;
    asm("{ .reg .u64 t; cvta.to.shared.u64 t, %1; cvt.u32.u64 %0, t; }" : "=r"(a) : "l"(p));
    return a;
}
#define SWZ128(o) ((o) ^ (((o) >> 3) & 0x70))

// pack two f32 -> bf16x2 (lo arg in low half)
__device__ __forceinline__ uint32_t pack_bf16x2(float lo, float hi) {
    uint32_t r;
    asm("cvt.rn.bf16x2.f32 %0, %1, %2;" : "=r"(r) : "f"(hi), "f"(lo));
    return r;
}

#if HAS_TCGEN05

__device__ __forceinline__ uint32_t elect_one() {
    uint32_t r;
    asm volatile("{ .reg .pred p; elect.sync _|p, 0xFFFFFFFF; selp.b32 %0, 1, 0, p; }" : "=r"(r));
    return r;
}

#define TC_ALLOC(smem_addr, ncols) \
    asm volatile("tcgen05.alloc.cta_group::1.sync.aligned.shared::cta.b32 [%0], %1;" \
                 :: "r"(smem_addr), "r"(ncols) : "memory")
#define TC_DEALLOC(tmem, ncols) \
    asm volatile("tcgen05.dealloc.cta_group::1.sync.aligned.b32 %0, %1;" :: "r"(tmem), "r"(ncols))
#define TC_COMMIT(mbar) \
    asm volatile("tcgen05.commit.cta_group::1.mbarrier::arrive::one.shared::cluster.b64 [%0];" \
                 :: "r"(mbar) : "memory")
#define TC_FENCE_AFTER()  asm volatile("tcgen05.fence::after_thread_sync;" ::: "memory")
#define TC_WAIT_LD()      asm volatile("tcgen05.wait::ld.sync.aligned;" ::: "memory")
#define FENCE_ASYNC_SHARED() asm volatile("fence.proxy.async.shared::cta;" ::: "memory")

#define CP_ASYNC16(dst, src) \
    asm volatile("cp.async.cg.shared.global [%0], [%1], 16;" :: "r"(dst), "l"(src) : "memory")
#define CP_COMMIT() asm volatile("cp.async.commit_group;" ::: "memory")
#define CP_WAIT0()  asm volatile("cp.async.wait_group 0;" ::: "memory")

#define MBAR_INIT(addr, cnt) \
    asm volatile("mbarrier.init.shared.b64 [%0], %1;" :: "r"(addr), "r"(cnt) : "memory")

#define MBAR_WAIT_PARITY(addr, parity) do { \
    uint32_t _mbar = (uint32_t)(addr); \
    uint32_t _par  = (uint32_t)(parity); \
    uint32_t _done; \
    asm volatile("{\n\t.reg .pred p;\n\t" \
        "mbarrier.try_wait.parity.acquire.cta.shared::cta.b64 p, [%1], %2;\n\t" \
        "selp.b32 %0, 1, 0, p;\n\t}" \
        : "=r"(_done) : "r"(_mbar), "r"(_par) : "memory"); \
    if (!_done) { \
        asm volatile("{\n\t.reg .pred P1;\n\t" \
            "WAIT_LOOP_%=:\n\t" \
            "mbarrier.try_wait.parity.acquire.cta.shared::cta.b64 P1, [%0], %1, 0x989680;\n\t" \
            "@P1 bra.uni WAIT_DONE_%=;\n\t" \
            "bra.uni WAIT_LOOP_%=;\n\t" \
            "WAIT_DONE_%=:\n\t}" \
            :: "r"(_mbar), "r"(_par) : "memory"); \
    } \
} while (0)

#define TC_LD_32X32B_X32(r, tmem_addr) \
    asm volatile( \
        "tcgen05.ld.sync.aligned.32x32b.x32.b32 " \
        "{%0, %1, %2, %3, %4, %5, %6, %7, " \
        " %8, %9, %10, %11, %12, %13, %14, %15, " \
        " %16, %17, %18, %19, %20, %21, %22, %23, " \
        " %24, %25, %26, %27, %28, %29, %30, %31}, [%32];" \
        : "=r"((r)[0]),  "=r"((r)[1]),  "=r"((r)[2]),  "=r"((r)[3]), \
          "=r"((r)[4]),  "=r"((r)[5]),  "=r"((r)[6]),  "=r"((r)[7]), \
          "=r"((r)[8]),  "=r"((r)[9]),  "=r"((r)[10]), "=r"((r)[11]), \
          "=r"((r)[12]), "=r"((r)[13]), "=r"((r)[14]), "=r"((r)[15]), \
          "=r"((r)[16]), "=r"((r)[17]), "=r"((r)[18]), "=r"((r)[19]), \
          "=r"((r)[20]), "=r"((r)[21]), "=r"((r)[22]), "=r"((r)[23]), \
          "=r"((r)[24]), "=r"((r)[25]), "=r"((r)[26]), "=r"((r)[27]), \
          "=r"((r)[28]), "=r"((r)[29]), "=r"((r)[30]), "=r"((r)[31]) \
        : "r"(tmem_addr))

// SW128 K-major smem descriptor (layout=2, version=1, SBO=64, LBO=1)
__device__ __forceinline__ uint64_t make_desc_sw128(uint32_t addr) {
    const uint64_t base = (uint64_t(2) << 61) | (uint64_t(1) << 46)
                        | (uint64_t(64) << 32) | (uint64_t(1) << 16);
    return base | ((uint64_t)(addr >> 4) & 0x3FFF);
}

// SS-mode f16-kind MMA, cta_group::1
__device__ __forceinline__ void mma_f16_ss(uint32_t d, uint64_t ad, uint64_t bd,
                                           uint32_t idesc, uint32_t en) {
    asm volatile(
        "{\n\t.reg .pred p;\n\t"
        "setp.ne.u32 p, %4, 0;\n\t"
        "tcgen05.mma.cta_group::1.kind::f16 [%0], %1, %2, %3, {%5,%5,%5,%5}, p;\n\t}"
        :: "r"(d), "l"(ad), "l"(bd), "r"(idesc), "r"(en), "r"(0u) : "memory");
}

#endif // HAS_TCGEN05

// ============================================================================
// Kernel 0a/0b: fp32 -> split bf16 (hi = truncate, lo = rn(x - hi))
// ============================================================================
__global__ __launch_bounds__(256)
void convert_x_kernel(const float* __restrict__ x)
{
    size_t idx = (size_t)blockIdx.x * 256 + threadIdx.x;   // one float4 each
    float4 p = __ldg((const float4*)(x + idx * 4));
    uint32_t w0 = __float_as_uint(p.x), w1 = __float_as_uint(p.y);
    uint32_t w2 = __float_as_uint(p.z), w3 = __float_as_uint(p.w);
    uint32_t h01 = __byte_perm(w0, w1, 0x7632);
    uint32_t h23 = __byte_perm(w2, w3, 0x7632);
    float l0 = p.x - __uint_as_float(w0 & 0xFFFF0000u);
    float l1 = p.y - __uint_as_float(w1 & 0xFFFF0000u);
    float l2 = p.z - __uint_as_float(w2 & 0xFFFF0000u);
    float l3 = p.w - __uint_as_float(w3 & 0xFFFF0000u);
    uint2 hv = make_uint2(h01, h23);
    uint2 lv = make_uint2(pack_bf16x2(l0, l1), pack_bf16x2(l2, l3));
    *(uint2*)(Xhi + idx * 4) = hv;
    *(uint2*)(Xlo + idx * 4) = lv;
}

__global__ __launch_bounds__(256)
void convert_w_kernel(const float* __restrict__ Wa, const float* __restrict__ Wu)
{
    size_t idx = (size_t)blockIdx.x * 256 + threadIdx.x;   // one float4 each
    size_t row = idx >> 8;                                  // DD/4 = 256 float4 per row
    size_t col4 = idx & 255;
    const float* src = (row < HH) ? (Wa + row * DD + col4 * 4)
                                  : (Wu + (row - HH) * DD + col4 * 4);
    float4 p = __ldg((const float4*)src);
    uint32_t w0 = __float_as_uint(p.x), w1 = __float_as_uint(p.y);
    uint32_t w2 = __float_as_uint(p.z), w3 = __float_as_uint(p.w);
    uint32_t h01 = __byte_perm(w0, w1, 0x7632);
    uint32_t h23 = __byte_perm(w2, w3, 0x7632);
    float l0 = p.x - __uint_as_float(w0 & 0xFFFF0000u);
    float l1 = p.y - __uint_as_float(w1 & 0xFFFF0000u);
    float l2 = p.z - __uint_as_float(w2 & 0xFFFF0000u);
    float l3 = p.w - __uint_as_float(w3 & 0xFFFF0000u);
    *(uint2*)(Whi + idx * 4) = make_uint2(h01, h23);
    *(uint2*)(Wlo + idx * 4) = make_uint2(pack_bf16x2(l0, l1), pack_bf16x2(l2, l3));
}

// ============================================================================
// Kernel 1: tcgen05 split-bf16 projection GEMM, cp.async-fed.
// C[m, n] = sum_d x[m,d] * W[n,d] + bias[n]
//         = Ahi·Bhi + Ahi·Blo + Alo·Bhi  (lo·lo dropped, ~2^-16 rel)
// Tile: M=128, N=256, K-chunk=64 bf16, double buffered. 256 threads.
// ============================================================================
#define TM 128
#define TN 256
#define KC 64
#define NCHUNK (DD / KC)     // 16

#define A_HI_OFF 0
#define A_LO_OFF 16384
#define B_HI_OFF 32768
#define B_LO_OFF 65536
#define STAGE_BYTES 98304
#define STAGE_BASE  1024
#define SMEM_TOTAL  (STAGE_BASE + 2 * STAGE_BYTES)   // 197632

__global__ __launch_bounds__(256, 1)
void proj_gemm_tc(const float* __restrict__ ba, const float* __restrict__ bu)
{
#if HAS_TCGEN05
    extern __shared__ char smem[];
    const uint32_t smb = smem_u32(smem);

    const uint32_t IDESC =
        (1u << 4) | (1u << 7) | (1u << 10) | ((TN / 8) << 17) | ((TM / 16) << 24);

    const int tid  = threadIdx.x;
    const int wid  = tid >> 5;
    const int lane = tid & 31;

    const int n0 = blockIdx.x * TN;       // 0..1792 (global over Wa||Wu)
    const int m0 = blockIdx.y * TM;
    const bool isA = (n0 < HH);
    const int ncol0 = isA ? n0 : (n0 - HH);
    const float* bias = (isA ? ba : bu) + ncol0;
    float* outb = isA ? A_buf : U_buf;

    if (wid == 0) TC_ALLOC(smb + 0, 256);
    if (tid == 0) {
        MBAR_INIT(smb + 8, 1);
        MBAR_INIT(smb + 16, 1);
    }
    __syncthreads();
    uint32_t tmem_base;
    asm volatile("ld.shared.b32 %0, [%1];" : "=r"(tmem_base) : "r"(smb + 0));

    const uint32_t mb[2] = { smb + 8, smb + 16 };
    uint32_t ph[2] = { 0, 0 };

    for (int c = 0; c < NCHUNK; ++c) {
        const int st = c & 1;
        const uint32_t sb = smb + STAGE_BASE + st * STAGE_BYTES;
        const int kc0 = c * KC;

        // wait until MMA from chunk c-2 released this stage
        if (c >= 2) { MBAR_WAIT_PARITY(mb[st], ph[st]); ph[st] ^= 1; }

        // ---- A tiles: 128 rows x 64 bf16 (hi & lo) via 16B cp.async
        {
            const uint32_t aHi = sb + A_HI_OFF, aLo = sb + A_LO_OFF;
#pragma unroll
            for (int j = 0; j < 4; j++) {
                int u = tid + j * 256;              // 0..1023
                int row = u >> 3, cb = u & 7;       // 8 x 16B per row
                uint32_t off = SWZ128((uint32_t)(row * 128 + cb * 16));
                const char* sH = (const char*)(Xhi + (size_t)(m0 + row) * DD + kc0) + cb * 16;
                const char* sL = (const char*)(Xlo + (size_t)(m0 + row) * DD + kc0) + cb * 16;
                CP_ASYNC16(aHi + off, sH);
                CP_ASYNC16(aLo + off, sL);
            }
        }
        // ---- B tiles: 256 rows x 64 bf16 (hi & lo)
        {
            const uint32_t bHi = sb + B_HI_OFF, bLo = sb + B_LO_OFF;
#pragma unroll
            for (int j = 0; j < 8; j++) {
                int u = tid + j * 256;              // 0..2047
                int row = u >> 3, cb = u & 7;
                uint32_t off = SWZ128((uint32_t)(row * 128 + cb * 16));
                const char* sH = (const char*)(Whi + (size_t)(n0 + row) * DD + kc0) + cb * 16;
                const char* sL = (const char*)(Wlo + (size_t)(n0 + row) * DD + kc0) + cb * 16;
                CP_ASYNC16(bHi + off, sH);
                CP_ASYNC16(bLo + off, sL);
            }
        }
        CP_COMMIT();
        CP_WAIT0();
        __syncthreads();   // tile complete for all threads

        if (wid == 0) {
            FENCE_ASYNC_SHARED();
            if (elect_one()) {
                uint64_t dAhi = make_desc_sw128(sb + A_HI_OFF);
                uint64_t dAlo = make_desc_sw128(sb + A_LO_OFF);
                uint64_t dBhi = make_desc_sw128(sb + B_HI_OFF);
                uint64_t dBlo = make_desc_sw128(sb + B_LO_OFF);
#pragma unroll
                for (int k = 0; k < 4; k++) {
                    uint32_t en0 = (c > 0 || k > 0) ? 1u : 0u;
                    mma_f16_ss(tmem_base, dAhi + k * 2, dBhi + k * 2, IDESC, en0);
                    mma_f16_ss(tmem_base, dAhi + k * 2, dBlo + k * 2, IDESC, 1u);
                    mma_f16_ss(tmem_base, dAlo + k * 2, dBhi + k * 2, IDESC, 1u);
                }
                TC_COMMIT(mb[st]);
            }
        }
    }

    // drain the last commit on each stage
    MBAR_WAIT_PARITY(mb[0], ph[0]);
    MBAR_WAIT_PARITY(mb[1], ph[1]);
    TC_FENCE_AFTER();
    __syncthreads();

    // ---- epilogue: TMEM -> (bias, sigmoid) -> smem transpose -> coalesced STG
    float* stg = (float*)(smem + STAGE_BASE);     // 128 x 65 fp32 staging
    const int half = wid >> 2;                     // col half within 64-slab
    const int subw = wid & 3;                      // TMEM subpartition rows
    const int rowl = subw * 32 + lane;

    for (int slab = 0; slab < 4; ++slab) {
        const int c0 = slab * 64;
        uint32_t regs[32];
        TC_LD_32X32B_X32(regs, tmem_base + c0 + half * 32);
        TC_WAIT_LD();
#pragma unroll
        for (int j = 0; j < 32; j++) {
            int n = c0 + half * 32 + j;
            float val = __uint_as_float(regs[j]) + __ldg(&bias[n]);
            if (isA) val = 1.f / (1.f + __expf(-val));
            stg[rowl * 65 + half * 32 + j] = val;
        }
        __syncthreads();
#pragma unroll
        for (int i = 0; i < 8; i++) {
            int idx = tid + i * 256;          // 0..2047
            int row = idx >> 4, c4 = idx & 15;
            const float* src = &stg[row * 65 + c4 * 4];   // scalar LDS (odd-row align)
            float4 vv;
            vv.x = src[0]; vv.y = src[1]; vv.z = src[2]; vv.w = src[3];
            *(float4*)(outb + (size_t)(m0 + row) * HH + ncol0 + c0 + c4 * 4) = vv;
        }
        __syncthreads();
    }

    if (wid == 0) TC_DEALLOC(tmem_base, 256);
#endif // HAS_TCGEN05
}

// ---------------------------------------------------------------------------
// Kernel 2: g projection. G[m, r] = sum_d x[m,d]*Wg[r,d] + bg[r]
// ---------------------------------------------------------------------------
__global__ __launch_bounds__(256)
void g_gemm_kernel(const float* __restrict__ x,
                   const float* __restrict__ Wg, const float* __restrict__ bg)
{
    __shared__ __align__(16) float Xs[16][512];
    __shared__ __align__(16) float Wgs[16][16];

    const int m0 = blockIdx.x * 512;
    const int tid = threadIdx.x;

    float acc0[RR], acc1[RR];
#pragma unroll
    for (int r = 0; r < RR; r++) { acc0[r] = 0.f; acc1[r] = 0.f; }

    for (int d0 = 0; d0 < DD; d0 += 16) {
        {
            int d = tid >> 4, rr = tid & 15;
            Wgs[d][rr] = Wg[(size_t)rr * DD + d0 + d];
        }
#pragma unroll
        for (int p = 0; p < 8; p++) {
            int row = (tid >> 2) + p * 64;
            int dc  = (tid & 3) * 4;
            float4 v4 = *(const float4*)(x + (size_t)(m0 + row) * DD + d0 + dc);
            Xs[dc + 0][row] = v4.x;
            Xs[dc + 1][row] = v4.y;
            Xs[dc + 2][row] = v4.z;
            Xs[dc + 3][row] = v4.w;
        }
        __syncthreads();

#pragma unroll
        for (int d = 0; d < 16; d++) {
            float xv0 = Xs[d][tid];
            float xv1 = Xs[d][tid + 256];
#pragma unroll
            for (int r = 0; r < RR; r++) {
                float wgv = Wgs[d][r];
                acc0[r] = fmaf(xv0, wgv, acc0[r]);
                acc1[r] = fmaf(xv1, wgv, acc1[r]);
            }
        }
        __syncthreads();
    }

    float bgv[RR];
#pragma unroll
    for (int r = 0; r < RR; r++) bgv[r] = bg[r];

    float* g0 = G_buf + (size_t)(m0 + tid) * RR;
    float* g1 = G_buf + (size_t)(m0 + tid + 256) * RR;
#pragma unroll
    for (int r = 0; r < RR; r += 4) {
        float4 o0, o1;
        o0.x = acc0[r+0]+bgv[r+0]; o0.y = acc0[r+1]+bgv[r+1];
        o0.z = acc0[r+2]+bgv[r+2]; o0.w = acc0[r+3]+bgv[r+3];
        o1.x = acc1[r+0]+bgv[r+0]; o1.y = acc1[r+1]+bgv[r+1];
        o1.z = acc1[r+2]+bgv[r+2]; o1.w = acc1[r+3]+bgv[r+3];
        *(float4*)(g0 + r) = o0;
        *(float4*)(g1 + r) = o1;
    }
}

// ---------------------------------------------------------------------------
// Kernel 3: sequential scan. 16 blocks (one per batch) x 1024 threads.
// s_t[h] = a_t[h]*s[h] + u_t[h] + sum_r u[h,r] * (g_t[r] * sum_h' s[h']*v[h',r])
// ---------------------------------------------------------------------------
__global__ __launch_bounds__(1024, 1)
void scan_kernel(const float* __restrict__ u_mat, const float* __restrict__ v_mat,
                 float* __restrict__ out)
{
    __shared__ __align__(16) float s_sm[HH];
    __shared__ __align__(16) float part[32][17];
    __shared__ __align__(16) float svg[16];
    __shared__ __align__(16) float g_sm[16];

    const int b    = blockIdx.x;
    const int tid  = threadIdx.x;
    const int wid  = tid >> 5;
    const int lane = tid & 31;
    const int r    = tid & 15;
    const int hg   = tid >> 4;

    float vreg[16], ureg[16];
#pragma unroll
    for (int k = 0; k < 16; k++) vreg[k] = v_mat[(size_t)(hg * 16 + k) * RR + r];
#pragma unroll
    for (int k = 0; k < 16; k++) ureg[k] = u_mat[(size_t)tid * RR + k];

    float s = 0.f;
    s_sm[tid] = 0.f;

    const size_t base = (size_t)b * SS;
    float g_cur = G_buf[(base + 0) * RR + r];
    __syncthreads();

    for (int t = 0; t < SS; t++) {
        float a_t = A_buf[(base + t) * HH + tid];
        float u_t = U_buf[(base + t) * HH + tid];
        if (tid < 16) g_sm[tid] = g_cur;

        // --- phase A: partial of (v^T s)[r] over h = hg*16 .. hg*16+15 ---
        float sv[16];
        const float4* sp = (const float4*)&s_sm[hg * 16];
        float4 s0 = sp[0], s1 = sp[1], s2 = sp[2], s3 = sp[3];
        sv[0]=s0.x; sv[1]=s0.y; sv[2]=s0.z; sv[3]=s0.w;
        sv[4]=s1.x; sv[5]=s1.y; sv[6]=s1.z; sv[7]=s1.w;
        sv[8]=s2.x; sv[9]=s2.y; sv[10]=s2.z; sv[11]=s2.w;
        sv[12]=s3.x; sv[13]=s3.y; sv[14]=s3.z; sv[15]=s3.w;

        float accA = 0.f, accB = 0.f;
#pragma unroll
        for (int k = 0; k < 16; k += 2) {
            accA = fmaf(sv[k],     vreg[k],     accA);
            accB = fmaf(sv[k + 1], vreg[k + 1], accB);
        }
        float acc = accA + accB;
        acc += __shfl_xor_sync(0xffffffffu, acc, 16);
        if (lane < 16) part[wid][lane] = acc;

        float g_nxt = (t + 1 < SS) ? G_buf[(base + t + 1) * RR + r] : 0.f;
        __syncthreads();   // bar1: partials + g_sm visible

        // --- reduce: warp w (w<16) sums 32 partials for residual index w ---
        if (wid < 16) {
            float pv = part[lane][wid];
            pv += __shfl_xor_sync(0xffffffffu, pv, 16);
            pv += __shfl_xor_sync(0xffffffffu, pv, 8);
            pv += __shfl_xor_sync(0xffffffffu, pv, 4);
            pv += __shfl_xor_sync(0xffffffffu, pv, 2);
            pv += __shfl_xor_sync(0xffffffffu, pv, 1);
            if (lane == 0) svg[wid] = g_sm[wid] * pv;
        }
        __syncthreads();   // bar2: svg visible

        // --- phase C: update state ---
        float cf[16];
        const float4* cp = (const float4*)&svg[0];
        float4 c0 = cp[0], c1 = cp[1], c2 = cp[2], c3 = cp[3];
        cf[0]=c0.x; cf[1]=c0.y; cf[2]=c0.z; cf[3]=c0.w;
        cf[4]=c1.x; cf[5]=c1.y; cf[6]=c1.z; cf[7]=c1.w;
        cf[8]=c2.x; cf[9]=c2.y; cf[10]=c2.z; cf[11]=c2.w;
        cf[12]=c3.x; cf[13]=c3.y; cf[14]=c3.z; cf[15]=c3.w;

        s = fmaf(a_t, s, u_t);
        float dA = 0.f, dB = 0.f;
#pragma unroll
        for (int k = 0; k < 16; k += 2) {
            dA = fmaf(cf[k],     ureg[k],     dA);
            dB = fmaf(cf[k + 1], ureg[k + 1], dB);
        }
        s += dA + dB;
        s_sm[tid] = s;
        g_cur = g_nxt;
        __syncthreads();   // bar3: state visible for next phase A
    }

    out[(size_t)b * HH + tid] = s;
}

// ---------------------------------------------------------------------------
extern "C" void kernel_launch(void* const* d_in, const int* in_sizes, int n_in,
                              void* d_out, int out_size)
{
    const float* x  = (const float*)d_in[0];
    const float* Wa = (const float*)d_in[1];
    const float* ba = (const float*)d_in[2];
    const float* Wg = (const float*)d_in[3];
    const float* bg = (const float*)d_in[4];
    const float* Wu = (const float*)d_in[5];
    const float* bu = (const float*)d_in[6];
    const float* u  = (const float*)d_in[7];
    const float* v  = (const float*)d_in[8];
    float* out = (float*)d_out;

    (void)in_sizes; (void)n_in; (void)out_size;

    cudaFuncSetAttribute(proj_gemm_tc, cudaFuncAttributeMaxDynamicSharedMemorySize, SMEM_TOTAL);

    convert_x_kernel<<<(MTOT * (DD / 4)) / 256, 256>>>(x);          // 32768 blocks
    convert_w_kernel<<<(NN2  * (DD / 4)) / 256, 256>>>(Wa, Wu);     // 2048 blocks
    proj_gemm_tc<<<dim3(NN2 / TN, MTOT / TM), 256, SMEM_TOTAL>>>(ba, bu);
    g_gemm_kernel<<<MTOT / 512, 256>>>(x, Wg, bg);
    scan_kernel<<<BB, 1024>>>(u, v, out);
}

// round 6
// speedup vs baseline: 2.5613x; 1.0724x over previous
#include <cuda_runtime.h>
#include <cuda_bf16.h>
#include <cstdint>

#define BB 16
#define SS 2048
#define DD 1024
#define HH 1024
#define RR 16
#define MTOT (BB*SS)   // 32768
#define NN2 2048       // Wa||Wu stacked rows

// tcgen05 only exists in the arch-specific (sm_103a/sm_100a) feature set.
// The harness also runs a compute_103 base-PTX pass; give it an empty body.
#if defined(__CUDA_ARCH_FEAT_SM103_ALL) || defined(__CUDA_ARCH_FEAT_SM100_ALL)
#define HAS_TCGEN05 1
#elif defined(__CUDA_ARCH_SPECIFIC__)
#if (__CUDA_ARCH_SPECIFIC__ == 1030) || (__CUDA_ARCH_SPECIFIC__ == 1000)
#define HAS_TCGEN05 1
#else
#define HAS_TCGEN05 0
#endif
#else
#define HAS_TCGEN05 0
#endif

// Scratch (module-load allocated, not runtime alloc)
__device__ float A_buf[(size_t)BB*SS*HH];   // sigmoid(x@Wa^T + ba)
__device__ float U_buf[(size_t)BB*SS*HH];   // x@Wu^T + bu
__device__ float G_buf[(size_t)BB*SS*RR];   // x@Wg^T + bg

// split-bf16 operand buffers (hi = truncated top16, lo = rn(x - hi))
__device__ __align__(16) __nv_bfloat16 Xhi[(size_t)MTOT*DD];
__device__ __align__(16) __nv_bfloat16 Xlo[(size_t)MTOT*DD];
__device__ __align__(16) __nv_bfloat16 Whi[(size_t)NN2*DD];
__device__ __align__(16) __nv_bfloat16 Wlo[(size_t)NN2*DD];

// ============================ helpers ============================
__device__ __forceinline__ uint32_t smem_u32(const void* p) {
    uint32_t a;
    asm("{ .reg .u64 t; cvta.to.shared.u64 t, %1; cvt.u32.u64 %0, t; }" : "=r"(a) : "l"(p));
    return a;
}
#define SWZ128(o) ((o) ^ (((o) >> 3) & 0x70))

// pack two f32 -> bf16x2 (lo arg in low half)
__device__ __forceinline__ uint32_t pack_bf16x2(float lo, float hi) {
    uint32_t r;
    asm("cvt.rn.bf16x2.f32 %0, %1, %2;" : "=r"(r) : "f"(hi), "f"(lo));
    return r;
}

#if HAS_TCGEN05

__device__ __forceinline__ uint32_t elect_one() {
    uint32_t r;
    asm volatile("{ .reg .pred p; elect.sync _|p, 0xFFFFFFFF; selp.b32 %0, 1, 0, p; }" : "=r"(r));
    return r;
}

#define TC_ALLOC(smem_addr, ncols) \
    asm volatile("tcgen05.alloc.cta_group::1.sync.aligned.shared::cta.b32 [%0], %1;" \
                 :: "r"(smem_addr), "r"(ncols) : "memory")
#define TC_DEALLOC(tmem, ncols) \
    asm volatile("tcgen05.dealloc.cta_group::1.sync.aligned.b32 %0, %1;" :: "r"(tmem), "r"(ncols))
#define TC_COMMIT(mbar) \
    asm volatile("tcgen05.commit.cta_group::1.mbarrier::arrive::one.shared::cluster.b64 [%0];" \
                 :: "r"(mbar) : "memory")
#define TC_FENCE_AFTER()  asm volatile("tcgen05.fence::after_thread_sync;" ::: "memory")
#define TC_WAIT_LD()      asm volatile("tcgen05.wait::ld.sync.aligned;" ::: "memory")
#define FENCE_ASYNC_SHARED() asm volatile("fence.proxy.async.shared::cta;" ::: "memory")

#define CP_ASYNC16(dst, src) \
    asm volatile("cp.async.cg.shared.global [%0], [%1], 16;" :: "r"(dst), "l"(src) : "memory")
#define CP_COMMIT() asm volatile("cp.async.commit_group;" ::: "memory")
#define CP_WAIT0()  asm volatile("cp.async.wait_group 0;" ::: "memory")

#define MBAR_INIT(addr, cnt) \
    asm volatile("mbarrier.init.shared.b64 [%0], %1;" :: "r"(addr), "r"(cnt) : "memory")

#define MBAR_WAIT_PARITY(addr, parity) do { \
    uint32_t _mbar = (uint32_t)(addr); \
    uint32_t _par  = (uint32_t)(parity); \
    uint32_t _done; \
    asm volatile("{\n\t.reg .pred p;\n\t" \
        "mbarrier.try_wait.parity.acquire.cta.shared::cta.b64 p, [%1], %2;\n\t" \
        "selp.b32 %0, 1, 0, p;\n\t}" \
        : "=r"(_done) : "r"(_mbar), "r"(_par) : "memory"); \
    if (!_done) { \
        asm volatile("{\n\t.reg .pred P1;\n\t" \
            "WAIT_LOOP_%=:\n\t" \
            "mbarrier.try_wait.parity.acquire.cta.shared::cta.b64 P1, [%0], %1, 0x989680;\n\t" \
            "@P1 bra.uni WAIT_DONE_%=;\n\t" \
            "bra.uni WAIT_LOOP_%=;\n\t" \
            "WAIT_DONE_%=:\n\t}" \
            :: "r"(_mbar), "r"(_par) : "memory"); \
    } \
} while (0)

#define TC_LD_32X32B_X32(r, tmem_addr) \
    asm volatile( \
        "tcgen05.ld.sync.aligned.32x32b.x32.b32 " \
        "{%0, %1, %2, %3, %4, %5, %6, %7, " \
        " %8, %9, %10, %11, %12, %13, %14, %15, " \
        " %16, %17, %18, %19, %20, %21, %22, %23, " \
        " %24, %25, %26, %27, %28, %29, %30, %31}, [%32];" \
        : "=r"((r)[0]),  "=r"((r)[1]),  "=r"((r)[2]),  "=r"((r)[3]), \
          "=r"((r)[4]),  "=r"((r)[5]),  "=r"((r)[6]),  "=r"((r)[7]), \
          "=r"((r)[8]),  "=r"((r)[9]),  "=r"((r)[10]), "=r"((r)[11]), \
          "=r"((r)[12]), "=r"((r)[13]), "=r"((r)[14]), "=r"((r)[15]), \
          "=r"((r)[16]), "=r"((r)[17]), "=r"((r)[18]), "=r"((r)[19]), \
          "=r"((r)[20]), "=r"((r)[21]), "=r"((r)[22]), "=r"((r)[23]), \
          "=r"((r)[24]), "=r"((r)[25]), "=r"((r)[26]), "=r"((r)[27]), \
          "=r"((r)[28]), "=r"((r)[29]), "=r"((r)[30]), "=r"((r)[31]) \
        : "r"(tmem_addr))

// SW128 K-major smem descriptor (layout=2, version=1, SBO=64, LBO=1)
__device__ __forceinline__ uint64_t make_desc_sw128(uint32_t addr) {
    const uint64_t base = (uint64_t(2) << 61) | (uint64_t(1) << 46)
                        | (uint64_t(64) << 32) | (uint64_t(1) << 16);
    return base | ((uint64_t)(addr >> 4) & 0x3FFF);
}

// SS-mode f16-kind MMA, cta_group::1
__device__ __forceinline__ void mma_f16_ss(uint32_t d, uint64_t ad, uint64_t bd,
                                           uint32_t idesc, uint32_t en) {
    asm volatile(
        "{\n\t.reg .pred p;\n\t"
        "setp.ne.u32 p, %4, 0;\n\t"
        "tcgen05.mma.cta_group::1.kind::f16 [%0], %1, %2, %3, {%5,%5,%5,%5}, p;\n\t}"
        :: "r"(d), "l"(ad), "l"(bd), "r"(idesc), "r"(en), "r"(0u) : "memory");
}

#endif // HAS_TCGEN05

// ============================================================================
// Kernel 0a/0b: fp32 -> split bf16 (hi = truncate, lo = rn(x - hi))
// ============================================================================
__global__ __launch_bounds__(256)
void convert_x_kernel(const float* __restrict__ x)
{
    size_t idx = (size_t)blockIdx.x * 256 + threadIdx.x;   // one float4 each
    float4 p = __ldg((const float4*)(x + idx * 4));
    uint32_t w0 = __float_as_uint(p.x), w1 = __float_as_uint(p.y);
    uint32_t w2 = __float_as_uint(p.z), w3 = __float_as_uint(p.w);
    uint32_t h01 = __byte_perm(w0, w1, 0x7632);
    uint32_t h23 = __byte_perm(w2, w3, 0x7632);
    float l0 = p.x - __uint_as_float(w0 & 0xFFFF0000u);
    float l1 = p.y - __uint_as_float(w1 & 0xFFFF0000u);
    float l2 = p.z - __uint_as_float(w2 & 0xFFFF0000u);
    float l3 = p.w - __uint_as_float(w3 & 0xFFFF0000u);
    *(uint2*)(Xhi + idx * 4) = make_uint2(h01, h23);
    *(uint2*)(Xlo + idx * 4) = make_uint2(pack_bf16x2(l0, l1), pack_bf16x2(l2, l3));
}

__global__ __launch_bounds__(256)
void convert_w_kernel(const float* __restrict__ Wa, const float* __restrict__ Wu)
{
    size_t idx = (size_t)blockIdx.x * 256 + threadIdx.x;   // one float4 each
    size_t row = idx >> 8;                                  // DD/4 = 256 float4 per row
    size_t col4 = idx & 255;
    const float* src = (row < HH) ? (Wa + row * DD + col4 * 4)
                                  : (Wu + (row - HH) * DD + col4 * 4);
    float4 p = __ldg((const float4*)src);
    uint32_t w0 = __float_as_uint(p.x), w1 = __float_as_uint(p.y);
    uint32_t w2 = __float_as_uint(p.z), w3 = __float_as_uint(p.w);
    uint32_t h01 = __byte_perm(w0, w1, 0x7632);
    uint32_t h23 = __byte_perm(w2, w3, 0x7632);
    float l0 = p.x - __uint_as_float(w0 & 0xFFFF0000u);
    float l1 = p.y - __uint_as_float(w1 & 0xFFFF0000u);
    float l2 = p.z - __uint_as_float(w2 & 0xFFFF0000u);
    float l3 = p.w - __uint_as_float(w3 & 0xFFFF0000u);
    *(uint2*)(Whi + idx * 4) = make_uint2(h01, h23);
    *(uint2*)(Wlo + idx * 4) = make_uint2(pack_bf16x2(l0, l1), pack_bf16x2(l2, l3));
}

// ============================================================================
// Kernel 1: tcgen05 split-bf16 projection GEMM, cp.async-fed.
// ============================================================================
#define TM 128
#define TN 256
#define KC 64
#define NCHUNK (DD / KC)     // 16

#define A_HI_OFF 0
#define A_LO_OFF 16384
#define B_HI_OFF 32768
#define B_LO_OFF 65536
#define STAGE_BYTES 98304
#define STAGE_BASE  1024
#define SMEM_TOTAL  (STAGE_BASE + 2 * STAGE_BYTES)   // 197632

__global__ __launch_bounds__(256, 1)
void proj_gemm_tc(const float* __restrict__ ba, const float* __restrict__ bu)
{
#if HAS_TCGEN05
    extern __shared__ char smem[];
    const uint32_t smb = smem_u32(smem);

    const uint32_t IDESC =
        (1u << 4) | (1u << 7) | (1u << 10) | ((TN / 8) << 17) | ((TM / 16) << 24);

    const int tid  = threadIdx.x;
    const int wid  = tid >> 5;
    const int lane = tid & 31;

    const int n0 = blockIdx.x * TN;       // 0..1792 (global over Wa||Wu)
    const int m0 = blockIdx.y * TM;
    const bool isA = (n0 < HH);
    const int ncol0 = isA ? n0 : (n0 - HH);
    const float* bias = (isA ? ba : bu) + ncol0;
    float* outb = isA ? A_buf : U_buf;

    if (wid == 0) TC_ALLOC(smb + 0, 256);
    if (tid == 0) {
        MBAR_INIT(smb + 8, 1);
        MBAR_INIT(smb + 16, 1);
    }
    __syncthreads();
    uint32_t tmem_base;
    asm volatile("ld.shared.b32 %0, [%1];" : "=r"(tmem_base) : "r"(smb + 0));

    const uint32_t mb[2] = { smb + 8, smb + 16 };
    uint32_t ph[2] = { 0, 0 };

    for (int c = 0; c < NCHUNK; ++c) {
        const int st = c & 1;
        const uint32_t sb = smb + STAGE_BASE + st * STAGE_BYTES;
        const int kc0 = c * KC;

        // wait until MMA from chunk c-2 released this stage
        if (c >= 2) { MBAR_WAIT_PARITY(mb[st], ph[st]); ph[st] ^= 1; }

        // ---- A tiles: 128 rows x 64 bf16 (hi & lo) via 16B cp.async
        {
            const uint32_t aHi = sb + A_HI_OFF, aLo = sb + A_LO_OFF;
#pragma unroll
            for (int j = 0; j < 4; j++) {
                int u = tid + j * 256;              // 0..1023
                int row = u >> 3, cb = u & 7;       // 8 x 16B per row
                uint32_t off = SWZ128((uint32_t)(row * 128 + cb * 16));
                const char* sH = (const char*)(Xhi + (size_t)(m0 + row) * DD + kc0) + cb * 16;
                const char* sL = (const char*)(Xlo + (size_t)(m0 + row) * DD + kc0) + cb * 16;
                CP_ASYNC16(aHi + off, sH);
                CP_ASYNC16(aLo + off, sL);
            }
        }
        // ---- B tiles: 256 rows x 64 bf16 (hi & lo)
        {
            const uint32_t bHi = sb + B_HI_OFF, bLo = sb + B_LO_OFF;
#pragma unroll
            for (int j = 0; j < 8; j++) {
                int u = tid + j * 256;              // 0..2047
                int row = u >> 3, cb = u & 7;
                uint32_t off = SWZ128((uint32_t)(row * 128 + cb * 16));
                const char* sH = (const char*)(Whi + (size_t)(n0 + row) * DD + kc0) + cb * 16;
                const char* sL = (const char*)(Wlo + (size_t)(n0 + row) * DD + kc0) + cb * 16;
                CP_ASYNC16(bHi + off, sH);
                CP_ASYNC16(bLo + off, sL);
            }
        }
        CP_COMMIT();
        CP_WAIT0();
        __syncthreads();   // tile complete for all threads

        if (wid == 0) {
            FENCE_ASYNC_SHARED();
            if (elect_one()) {
                uint64_t dAhi = make_desc_sw128(sb + A_HI_OFF);
                uint64_t dAlo = make_desc_sw128(sb + A_LO_OFF);
                uint64_t dBhi = make_desc_sw128(sb + B_HI_OFF);
                uint64_t dBlo = make_desc_sw128(sb + B_LO_OFF);
#pragma unroll
                for (int k = 0; k < 4; k++) {
                    uint32_t en0 = (c > 0 || k > 0) ? 1u : 0u;
                    mma_f16_ss(tmem_base, dAhi + k * 2, dBhi + k * 2, IDESC, en0);
                    mma_f16_ss(tmem_base, dAhi + k * 2, dBlo + k * 2, IDESC, 1u);
                    mma_f16_ss(tmem_base, dAlo + k * 2, dBhi + k * 2, IDESC, 1u);
                }
                TC_COMMIT(mb[st]);
            }
        }
    }

    // drain the last commit on each stage
    MBAR_WAIT_PARITY(mb[0], ph[0]);
    MBAR_WAIT_PARITY(mb[1], ph[1]);
    TC_FENCE_AFTER();
    __syncthreads();

    // ---- epilogue: TMEM -> (bias, sigmoid) -> smem transpose -> coalesced STG
    float* stg = (float*)(smem + STAGE_BASE);     // 128 x 65 fp32 staging
    const int half = wid >> 2;                     // col half within 64-slab
    const int subw = wid & 3;                      // TMEM subpartition rows
    const int rowl = subw * 32 + lane;

    for (int slab = 0; slab < 4; ++slab) {
        const int c0 = slab * 64;
        uint32_t regs[32];
        TC_LD_32X32B_X32(regs, tmem_base + c0 + half * 32);
        TC_WAIT_LD();
#pragma unroll
        for (int j = 0; j < 32; j++) {
            int n = c0 + half * 32 + j;
            float val = __uint_as_float(regs[j]) + __ldg(&bias[n]);
            if (isA) val = 1.f / (1.f + __expf(-val));
            stg[rowl * 65 + half * 32 + j] = val;
        }
        __syncthreads();
#pragma unroll
        for (int i = 0; i < 8; i++) {
            int idx = tid + i * 256;          // 0..2047
            int row = idx >> 4, c4 = idx & 15;
            const float* src = &stg[row * 65 + c4 * 4];   // scalar LDS (odd-row align)
            float4 vv;
            vv.x = src[0]; vv.y = src[1]; vv.z = src[2]; vv.w = src[3];
            *(float4*)(outb + (size_t)(m0 + row) * HH + ncol0 + c0 + c4 * 4) = vv;
        }
        __syncthreads();
    }

    if (wid == 0) TC_DEALLOC(tmem_base, 256);
#endif // HAS_TCGEN05
}

// ---------------------------------------------------------------------------
// Kernel 2: g projection. G[m, r] = sum_d x[m,d]*Wg[r,d] + bg[r]
// 128 blocks x 256 threads, 256 rows/block, 1 row per thread.
// ---------------------------------------------------------------------------
__global__ __launch_bounds__(256)
void g_gemm_kernel(const float* __restrict__ x,
                   const float* __restrict__ Wg, const float* __restrict__ bg)
{
    __shared__ __align__(16) float Xs[16][260];    // pad 260: conflict-free stores
    __shared__ __align__(16) float Wgs[16][16];

    const int m0 = blockIdx.x * 256;
    const int tid = threadIdx.x;

    float acc[RR];
#pragma unroll
    for (int r = 0; r < RR; r++) acc[r] = 0.f;

    for (int d0 = 0; d0 < DD; d0 += 16) {
        {
            int d = tid >> 4, rr = tid & 15;
            Wgs[d][rr] = Wg[(size_t)rr * DD + d0 + d];
        }
#pragma unroll
        for (int p = 0; p < 4; p++) {
            int row = (tid >> 2) + p * 64;
            int dc  = (tid & 3) * 4;
            float4 v4 = *(const float4*)(x + (size_t)(m0 + row) * DD + d0 + dc);
            Xs[dc + 0][row] = v4.x;
            Xs[dc + 1][row] = v4.y;
            Xs[dc + 2][row] = v4.z;
            Xs[dc + 3][row] = v4.w;
        }
        __syncthreads();

#pragma unroll
        for (int d = 0; d < 16; d++) {
            float xv = Xs[d][tid];
#pragma unroll
            for (int r = 0; r < RR; r++)
                acc[r] = fmaf(xv, Wgs[d][r], acc[r]);
        }
        __syncthreads();
    }

    float* g0 = G_buf + (size_t)(m0 + tid) * RR;
#pragma unroll
    for (int r = 0; r < RR; r += 4) {
        float4 o0;
        o0.x = acc[r+0]+bg[r+0]; o0.y = acc[r+1]+bg[r+1];
        o0.z = acc[r+2]+bg[r+2]; o0.w = acc[r+3]+bg[r+3];
        *(float4*)(g0 + r) = o0;
    }
}

// ---------------------------------------------------------------------------
// Kernel 3: sequential scan. 16 blocks (one per batch) x 1024 threads.
// Cross-iteration prefetch of a/u/g removes DRAM latency from the chain.
// ---------------------------------------------------------------------------
__global__ __launch_bounds__(1024, 1)
void scan_kernel(const float* __restrict__ u_mat, const float* __restrict__ v_mat,
                 float* __restrict__ out)
{
    __shared__ __align__(16) float s_sm[HH];
    __shared__ __align__(16) float part[32][17];
    __shared__ __align__(16) float svg[16];
    __shared__ __align__(16) float g_sm[16];

    const int b    = blockIdx.x;
    const int tid  = threadIdx.x;
    const int wid  = tid >> 5;
    const int lane = tid & 31;
    const int r    = tid & 15;
    const int hg   = tid >> 4;

    float vreg[16], ureg[16];
#pragma unroll
    for (int k = 0; k < 16; k++) vreg[k] = v_mat[(size_t)(hg * 16 + k) * RR + r];
#pragma unroll
    for (int k = 0; k < 16; k++) ureg[k] = u_mat[(size_t)tid * RR + k];

    float s = 0.f;
    s_sm[tid] = 0.f;

    const size_t base = (size_t)b * SS;
    // prefetch step 0
    float a_cur = A_buf[(base + 0) * HH + tid];
    float u_cur = U_buf[(base + 0) * HH + tid];
    float g_cur = G_buf[(base + 0) * RR + r];
    __syncthreads();

    for (int t = 0; t < SS; t++) {
        // ---- issue prefetch for t+1 (consumed next iteration) ----
        float a_nxt = 0.f, u_nxt = 0.f, g_nxt = 0.f;
        if (t + 1 < SS) {
            a_nxt = A_buf[(base + t + 1) * HH + tid];
            u_nxt = U_buf[(base + t + 1) * HH + tid];
            g_nxt = G_buf[(base + t + 1) * RR + r];
        }
        if (tid < 16) g_sm[tid] = g_cur;

        // --- phase A: partial of (v^T s)[r] over h = hg*16 .. hg*16+15 ---
        float sv[16];
        const float4* sp = (const float4*)&s_sm[hg * 16];
        float4 s0 = sp[0], s1 = sp[1], s2 = sp[2], s3 = sp[3];
        sv[0]=s0.x; sv[1]=s0.y; sv[2]=s0.z; sv[3]=s0.w;
        sv[4]=s1.x; sv[5]=s1.y; sv[6]=s1.z; sv[7]=s1.w;
        sv[8]=s2.x; sv[9]=s2.y; sv[10]=s2.z; sv[11]=s2.w;
        sv[12]=s3.x; sv[13]=s3.y; sv[14]=s3.z; sv[15]=s3.w;

        float accA = 0.f, accB = 0.f;
#pragma unroll
        for (int k = 0; k < 16; k += 2) {
            accA = fmaf(sv[k],     vreg[k],     accA);
            accB = fmaf(sv[k + 1], vreg[k + 1], accB);
        }
        float acc = accA + accB;
        acc += __shfl_xor_sync(0xffffffffu, acc, 16);
        if (lane < 16) part[wid][lane] = acc;
        __syncthreads();   // bar1: partials + g_sm visible

        // --- reduce: warp w (w<16) sums 32 partials for residual index w ---
        if (wid < 16) {
            float pv = part[lane][wid];
            pv += __shfl_xor_sync(0xffffffffu, pv, 16);
            pv += __shfl_xor_sync(0xffffffffu, pv, 8);
            pv += __shfl_xor_sync(0xffffffffu, pv, 4);
            pv += __shfl_xor_sync(0xffffffffu, pv, 2);
            pv += __shfl_xor_sync(0xffffffffu, pv, 1);
            if (lane == 0) svg[wid] = g_sm[wid] * pv;
        }
        __syncthreads();   // bar2: svg visible

        // --- phase C: update state ---
        float cf[16];
        const float4* cp = (const float4*)&svg[0];
        float4 c0 = cp[0], c1 = cp[1], c2 = cp[2], c3 = cp[3];
        cf[0]=c0.x; cf[1]=c0.y; cf[2]=c0.z; cf[3]=c0.w;
        cf[4]=c1.x; cf[5]=c1.y; cf[6]=c1.z; cf[7]=c1.w;
        cf[8]=c2.x; cf[9]=c2.y; cf[10]=c2.z; cf[11]=c2.w;
        cf[12]=c3.x; cf[13]=c3.y; cf[14]=c3.z; cf[15]=c3.w;

        s = fmaf(a_cur, s, u_cur);
        float dA = 0.f, dB = 0.f;
#pragma unroll
        for (int k = 0; k < 16; k += 2) {
            dA = fmaf(cf[k],     ureg[k],     dA);
            dB = fmaf(cf[k + 1], ureg[k + 1], dB);
        }
        s += dA + dB;
        s_sm[tid] = s;
        a_cur = a_nxt; u_cur = u_nxt; g_cur = g_nxt;
        __syncthreads();   // bar3: state visible for next phase A
    }

    out[(size_t)b * HH + tid] = s;
}

// ---------------------------------------------------------------------------
extern "C" void kernel_launch(void* const* d_in, const int* in_sizes, int n_in,
                              void* d_out, int out_size)
{
    const float* x  = (const float*)d_in[0];
    const float* Wa = (const float*)d_in[1];
    const float* ba = (const float*)d_in[2];
    const float* Wg = (const float*)d_in[3];
    const float* bg = (const float*)d_in[4];
    const float* Wu = (const float*)d_in[5];
    const float* bu = (const float*)d_in[6];
    const float* u  = (const float*)d_in[7];
    const float* v  = (const float*)d_in[8];
    float* out = (float*)d_out;

    (void)in_sizes; (void)n_in; (void)out_size;

    cudaFuncSetAttribute(proj_gemm_tc, cudaFuncAttributeMaxDynamicSharedMemorySize, SMEM_TOTAL);

    convert_x_kernel<<<(MTOT * (DD / 4)) / 256, 256>>>(x);          // pos 0
    convert_w_kernel<<<(NN2  * (DD / 4)) / 256, 256>>>(Wa, Wu);     // pos 1
    g_gemm_kernel<<<MTOT / 256, 256>>>(x, Wg, bg);                  // pos 2
    proj_gemm_tc<<<dim3(NN2 / TN, MTOT / TM), 256, SMEM_TOTAL>>>(ba, bu);  // pos 3 (profiled slot)
    scan_kernel<<<BB, 1024>>>(u, v, out);                           // pos 4
}